// round 8
// baseline (speedup 1.0000x reference)
#include <cuda_runtime.h>
#include <cuda_fp16.h>
#include <cstdint>

#define N_NODES 10000
#define N_EDGES 640000
#define K_DIM   128

// ---------------- scratch -------------------------------------------------------
__device__ __align__(128) int    g_deg[N_NODES];
__device__ __align__(128) int    g_off[N_NODES + 1];
__device__ __align__(128) int    g_rank[N_EDGES];       // per-edge rank within dst
__device__ __align__(128) int    g_csr[N_EDGES];
__device__ __align__(128) __half g_yn[N_NODES * 128];   // neighbor projections (fp16)
__device__ __align__(128) float  g_ys[N_NODES * 128];   // self projections (fp32)
__device__ __align__(128) float  g_h0[N_NODES * 128];
__device__ __align__(128) float  g_h1[N_NODES * 128];
__device__ __align__(128) __half g_bw0[256 * 256];      // layer weights: [NOUT][hi128|lo128]
__device__ __align__(128) __half g_bw1[256 * 256];
__device__ __align__(128) __half g_bw2[128 * 256];

// ---------------- small PTX helpers ----------------------------------------------
__device__ __forceinline__ uint32_t smem_u32(const void* p) {
    uint32_t a;
    asm("{ .reg .u64 t; cvta.to.shared.u64 t, %1; cvt.u32.u64 %0, t; }" : "=r"(a) : "l"(p));
    return a;
}
__device__ __forceinline__ void ldsm_x4(uint32_t& r0, uint32_t& r1, uint32_t& r2,
                                        uint32_t& r3, uint32_t addr) {
    asm volatile("ldmatrix.sync.aligned.m8n8.x4.shared.b16 {%0,%1,%2,%3}, [%4];"
                 : "=r"(r0), "=r"(r1), "=r"(r2), "=r"(r3) : "r"(addr));
}
__device__ __forceinline__ void mma16816(float* d, uint32_t a0, uint32_t a1,
                                         uint32_t a2, uint32_t a3,
                                         uint32_t b0, uint32_t b1) {
    asm volatile(
        "mma.sync.aligned.m16n8k16.row.col.f32.f16.f16.f32 "
        "{%0,%1,%2,%3},{%4,%5,%6,%7},{%8,%9},{%0,%1,%2,%3};"
        : "+f"(d[0]), "+f"(d[1]), "+f"(d[2]), "+f"(d[3])
        : "r"(a0), "r"(a1), "r"(a2), "r"(a3), "r"(b0), "r"(b1));
}
__device__ __forceinline__ uint2 ldg_cg_u2(const void* p) {
    uint2 v;
    asm volatile("ld.global.cg.v2.u32 {%0,%1}, [%2];"
                 : "=r"(v.x), "=r"(v.y) : "l"(p));
    return v;
}
__device__ __forceinline__ unsigned ldg_cg_u1(const void* p) {
    unsigned v;
    asm volatile("ld.global.cg.u32 %0, [%1];" : "=r"(v) : "l"(p));
    return v;
}

// ---------------- prep: build hi/lo weights for all layers (NO deg zero here) ----
__global__ void prep_all_k(const float* __restrict__ Wn0, const float* __restrict__ Ws0,
                           const float* __restrict__ Wn1, const float* __restrict__ Ws1,
                           const float* __restrict__ Wn2, const float* __restrict__ Ws2) {
    int idx = blockIdx.x * blockDim.x + threadIdx.x;
    if (idx >= 81920) return;
    int base, DOUT;
    const float *Wn, *Ws; __half* Bw;
    if (idx < 32768)      { base = idx;         DOUT = 128; Wn = Wn0; Ws = Ws0; Bw = g_bw0; }
    else if (idx < 65536) { base = idx - 32768; DOUT = 128; Wn = Wn1; Ws = Ws1; Bw = g_bw1; }
    else                  { base = idx - 65536; DOUT = 64;  Wn = Wn2; Ws = Ws2; Bw = g_bw2; }
    int n = base >> 7, k = base & 127;
    const float* W = (n < DOUT) ? Wn : Ws;
    int nn = (n < DOUT) ? n : n - DOUT;
    float v = W[(size_t)k * DOUT + nn];
    __half h = __float2half_rn(v);
    __half l = __float2half_rn(v - __half2float(h));
    Bw[(size_t)n * 256 + k]       = h;
    Bw[(size_t)n * 256 + 128 + k] = l;
}

// ---------------- CSR build ----------------------------------------------------
__global__ void hist_k(const int* __restrict__ dst) {
    int e4 = blockIdx.x * blockDim.x + threadIdx.x;
    if (e4 * 4 < N_EDGES) {
        int4 d = ((const int4*)dst)[e4];
        int4 r;
        r.x = atomicAdd(&g_deg[d.x], 1);
        r.y = atomicAdd(&g_deg[d.y], 1);
        r.z = atomicAdd(&g_deg[d.z], 1);
        r.w = atomicAdd(&g_deg[d.w], 1);
        ((int4*)g_rank)[e4] = r;
    }
}

__global__ void scan_k() {
    __shared__ int wsum[32];
    int t = threadIdx.x;
    int base = t * 10;
    int loc[10];
    int s = 0;
    #pragma unroll
    for (int i = 0; i < 10; i++) {
        int idx = base + i;
        int v = (idx < N_NODES) ? g_deg[idx] : 0;
        loc[i] = s; s += v;
    }
    int lane = t & 31, w = t >> 5;
    int x = s;
    #pragma unroll
    for (int o = 1; o < 32; o <<= 1) {
        int y = __shfl_up_sync(0xffffffff, x, o);
        if (lane >= o) x += y;
    }
    if (lane == 31) wsum[w] = x;
    __syncthreads();
    if (w == 0) {
        int y = wsum[lane];
        #pragma unroll
        for (int o = 1; o < 32; o <<= 1) {
            int z = __shfl_up_sync(0xffffffff, y, o);
            if (lane >= o) y += z;
        }
        wsum[lane] = y;
    }
    __syncthreads();
    int warp_excl = (w == 0) ? 0 : wsum[w - 1];
    int texcl = warp_excl + x - s;
    #pragma unroll
    for (int i = 0; i < 10; i++) {
        int idx = base + i;
        if (idx < N_NODES) g_off[idx] = texcl + loc[i];
    }
    if (t == 1023) g_off[N_NODES] = warp_excl + x;
}

__global__ void scatter_k(const int* __restrict__ src, const int* __restrict__ dst) {
    int e4 = blockIdx.x * blockDim.x + threadIdx.x;
    if (e4 * 4 < N_EDGES) {
        int4 s = ((const int4*)src)[e4];
        int4 d = ((const int4*)dst)[e4];
        int4 r = ((const int4*)g_rank)[e4];
        g_csr[__ldg(&g_off[d.x]) + r.x] = s.x;
        g_csr[__ldg(&g_off[d.y]) + r.y] = s.y;
        g_csr[__ldg(&g_off[d.z]) + r.z] = s.z;
        g_csr[__ldg(&g_off[d.w]) + r.w] = s.w;
    }
}

// ---------------- HMMA GEMM: Y = X @ [W_neigh | W_self], hi/lo fp16 split --------
static constexpr int APAD  = 136;
static constexpr int A_HI  = 0;
static constexpr int A_LO  = 128 * APAD * 2;
static constexpr int B_HI  = 2 * 128 * APAD * 2;
static constexpr int B_LO  = B_HI + 128 * APAD * 2;
static constexpr int GEMM_SMEM = B_LO + 128 * APAD * 2;

template <int DOUT>
__global__ void __launch_bounds__(256, 1)
gemm_mma_k(const float* __restrict__ X, const __half* __restrict__ Bw,
           __half* __restrict__ Yn, float* __restrict__ Ys) {
    extern __shared__ char sm[];
    const uint32_t sb = smem_u32(sm);
    const int tid  = threadIdx.x;
    const int lane = tid & 31;
    const int wid  = tid >> 5;
    const int row0 = blockIdx.x * 128;
    const int col0 = blockIdx.y * 128;

    #pragma unroll
    for (int i = 0; i < 16; i++) {
        int idx = i * 256 + tid;
        int r = idx >> 5, q = idx & 31;
        int grow = row0 + r;
        float4 v = make_float4(0.f, 0.f, 0.f, 0.f);
        if (grow < N_NODES) v = *(const float4*)(X + (size_t)grow * K_DIM + q * 4);
        __half hx = __float2half_rn(v.x), hy = __float2half_rn(v.y);
        __half hz = __float2half_rn(v.z), hw = __float2half_rn(v.w);
        __half2 hp0 = __halves2half2(hx, hy), hp1 = __halves2half2(hz, hw);
        __half2 lp0 = __floats2half2_rn(v.x - __half2float(hx), v.y - __half2float(hy));
        __half2 lp1 = __floats2half2_rn(v.z - __half2float(hz), v.w - __half2float(hw));
        uint32_t off = (uint32_t)(r * APAD + q * 4) * 2;
        uint2 uh; uh.x = *(uint32_t*)&hp0; uh.y = *(uint32_t*)&hp1;
        uint2 ul; ul.x = *(uint32_t*)&lp0; ul.y = *(uint32_t*)&lp1;
        *(uint2*)(sm + A_HI + off) = uh;
        *(uint2*)(sm + A_LO + off) = ul;
    }

    #pragma unroll
    for (int i = 0; i < 16; i++) {
        int idx = i * 256 + tid;
        int n = idx >> 5, q = idx & 31;
        uint4 v = *(const uint4*)(Bw + (size_t)(col0 + n) * 256 + q * 8);
        int base = (q < 16) ? B_HI : B_LO;
        uint32_t off = (uint32_t)(n * APAD + (q & 15) * 8) * 2;
        *(uint4*)(sm + base + off) = v;
    }
    __syncthreads();

    const int warp_m = wid >> 1;
    const int warp_n = wid & 1;
    const uint32_t lrow = (uint32_t)(lane & 15);
    const uint32_t lcol = (uint32_t)(lane >> 4) * 16;

    float acc[2][8][4];
    #pragma unroll
    for (int a = 0; a < 2; a++)
        #pragma unroll
        for (int b = 0; b < 8; b++)
            #pragma unroll
            for (int c = 0; c < 4; c++) acc[a][b][c] = 0.f;

    #pragma unroll
    for (int p = 0; p < 3; p++) {
        const uint32_t Ab = sb + (p == 1 ? A_LO : A_HI);
        const uint32_t Bb = sb + (p == 2 ? B_LO : B_HI);
        const uint32_t a0addr = Ab + (warp_m * 32 + lrow) * (APAD * 2) + lcol;
        const uint32_t b0addr = Bb + (warp_n * 64 + lrow) * (APAD * 2) + lcol;
        #pragma unroll
        for (int ks = 0; ks < 8; ks++) {
            const uint32_t koff = (uint32_t)ks * 32;
            uint32_t a0, a1, a2, a3, c0, c1, c2, c3;
            ldsm_x4(a0, a1, a2, a3, a0addr + koff);
            ldsm_x4(c0, c1, c2, c3, a0addr + 16 * (APAD * 2) + koff);
            #pragma unroll
            for (int nb = 0; nb < 4; nb++) {
                uint32_t b0, b1, b2, b3;
                ldsm_x4(b0, b1, b2, b3, b0addr + nb * 16 * (APAD * 2) + koff);
                mma16816(acc[0][nb * 2],     a0, a1, a2, a3, b0, b2);
                mma16816(acc[0][nb * 2 + 1], a0, a1, a2, a3, b1, b3);
                mma16816(acc[1][nb * 2],     c0, c1, c2, c3, b0, b2);
                mma16816(acc[1][nb * 2 + 1], c0, c1, c2, c3, b1, b3);
            }
        }
    }

    #pragma unroll
    for (int mi = 0; mi < 2; mi++) {
        int row_lo = row0 + warp_m * 32 + mi * 16 + (lane >> 2);
        int row_hi = row_lo + 8;
        #pragma unroll
        for (int ni = 0; ni < 8; ni++) {
            float* d = acc[mi][ni];
            int colg = col0 + warp_n * 64 + ni * 8 + (lane & 3) * 2;
            if (colg < DOUT) {
                if (row_lo < N_NODES)
                    *(__half2*)&Yn[(size_t)row_lo * DOUT + colg] = __floats2half2_rn(d[0], d[1]);
                if (row_hi < N_NODES)
                    *(__half2*)&Yn[(size_t)row_hi * DOUT + colg] = __floats2half2_rn(d[2], d[3]);
            } else {
                int c = colg - DOUT;
                if (row_lo < N_NODES)
                    *(float2*)&Ys[(size_t)row_lo * DOUT + c] = make_float2(d[0], d[1]);
                if (row_hi < N_NODES)
                    *(float2*)&Ys[(size_t)row_hi * DOUT + c] = make_float2(d[2], d[3]);
            }
        }
    }
}

// ---------------- aggregate: out = relu?(mean(Yn[csr]) + Ys + bias) -------------
// One warp per node. 32-neighbor chunks: coalesced index load + shfl broadcast,
// 16 gathers in flight per lane (.cg, skip L1).
template <int DOUT, bool RELU>
__global__ void aggregate_k(const __half* __restrict__ Yn,
                            const float*  __restrict__ Ys,
                            const float*  __restrict__ bias,
                            float*        __restrict__ out) {
    constexpr int V = DOUT / 32;
    int gw = (blockIdx.x * blockDim.x + threadIdx.x) >> 5;
    if (gw >= N_NODES) return;
    int lane = threadIdx.x & 31;

    int beg = g_off[gw], end = g_off[gw + 1];
    float acc[V];
    #pragma unroll
    for (int v = 0; v < V; v++) acc[v] = 0.f;

    const __half* base = Yn + lane * V;
    int j = beg;

    // full 32-neighbor chunks
    for (; j + 32 <= end; j += 32) {
        int myidx = __ldg(&g_csr[j + lane]);
        #pragma unroll
        for (int h = 0; h < 2; h++) {
            if constexpr (V == 4) {
                uint2 uu[16];
                #pragma unroll
                for (int u = 0; u < 16; u++) {
                    int s = __shfl_sync(0xffffffff, myidx, h * 16 + u);
                    uu[u] = ldg_cg_u2(base + (size_t)s * DOUT);
                }
                #pragma unroll
                for (int u = 0; u < 16; u++) {
                    float2 a = __half22float2(*(__half2*)&uu[u].x);
                    float2 b = __half22float2(*(__half2*)&uu[u].y);
                    acc[0] += a.x; acc[1] += a.y; acc[2] += b.x; acc[3] += b.y;
                }
            } else {
                unsigned uu[16];
                #pragma unroll
                for (int u = 0; u < 16; u++) {
                    int s = __shfl_sync(0xffffffff, myidx, h * 16 + u);
                    uu[u] = ldg_cg_u1(base + (size_t)s * DOUT);
                }
                #pragma unroll
                for (int u = 0; u < 16; u++) {
                    float2 a = __half22float2(*(__half2*)&uu[u]);
                    acc[0] += a.x; acc[1] += a.y;
                }
            }
        }
    }
    // remainder (<32): coalesced index load once, guarded shfl gathers
    int rem = end - j;
    if (rem > 0) {
        int myidx = (lane < rem) ? __ldg(&g_csr[j + lane]) : 0;
        if constexpr (V == 4) {
            for (int u = 0; u < rem; u++) {
                int s = __shfl_sync(0xffffffff, myidx, u);
                uint2 u0 = ldg_cg_u2(base + (size_t)s * DOUT);
                float2 a = __half22float2(*(__half2*)&u0.x);
                float2 b = __half22float2(*(__half2*)&u0.y);
                acc[0] += a.x; acc[1] += a.y; acc[2] += b.x; acc[3] += b.y;
            }
        } else {
            for (int u = 0; u < rem; u++) {
                int s = __shfl_sync(0xffffffff, myidx, u);
                unsigned u0 = ldg_cg_u1(base + (size_t)s * DOUT);
                float2 a = __half22float2(*(__half2*)&u0);
                acc[0] += a.x; acc[1] += a.y;
            }
        }
    }

    float inv = 1.0f / fmaxf((float)(end - beg), 1.0f);

    if constexpr (V == 4) {
        float4 s  = *(const float4*)(Ys + (size_t)gw * DOUT + lane * 4);
        float4 bb = *(const float4*)(bias + lane * 4);
        float4 o;
        o.x = acc[0] * inv + s.x + bb.x;
        o.y = acc[1] * inv + s.y + bb.y;
        o.z = acc[2] * inv + s.z + bb.z;
        o.w = acc[3] * inv + s.w + bb.w;
        if (RELU) {
            o.x = fmaxf(o.x, 0.f); o.y = fmaxf(o.y, 0.f);
            o.z = fmaxf(o.z, 0.f); o.w = fmaxf(o.w, 0.f);
        }
        *(float4*)(out + (size_t)gw * DOUT + lane * 4) = o;
    } else {
        float2 s  = *(const float2*)(Ys + (size_t)gw * DOUT + lane * 2);
        float2 bb = *(const float2*)(bias + lane * 2);
        float2 o;
        o.x = acc[0] * inv + s.x + bb.x;
        o.y = acc[1] * inv + s.y + bb.y;
        if (RELU) { o.x = fmaxf(o.x, 0.f); o.y = fmaxf(o.y, 0.f); }
        *(float2*)(out + (size_t)gw * DOUT + lane * 2) = o;
    }
}

// ---------------- launcher -------------------------------------------------------
extern "C" void kernel_launch(void* const* d_in, const int* in_sizes, int n_in,
                              void* d_out, int out_size) {
    const float* inputs  = (const float*)d_in[0];
    const float* W_self0 = (const float*)d_in[1];
    const float* W_nei0  = (const float*)d_in[2];
    const float* b0      = (const float*)d_in[3];
    const float* W_self1 = (const float*)d_in[4];
    const float* W_nei1  = (const float*)d_in[5];
    const float* b1      = (const float*)d_in[6];
    const float* W_self2 = (const float*)d_in[7];
    const float* W_nei2  = (const float*)d_in[8];
    const float* b2      = (const float*)d_in[9];
    const int* edge_src  = (const int*)d_in[10];
    const int* edge_dst  = (const int*)d_in[11];
    float* out = (float*)d_out;

    __half *yn, *bw0, *bw1, *bw2; float *ys, *h0, *h1; int* deg;
    cudaGetSymbolAddress((void**)&yn,  g_yn);
    cudaGetSymbolAddress((void**)&ys,  g_ys);
    cudaGetSymbolAddress((void**)&h0,  g_h0);
    cudaGetSymbolAddress((void**)&h1,  g_h1);
    cudaGetSymbolAddress((void**)&bw0, g_bw0);
    cudaGetSymbolAddress((void**)&bw1, g_bw1);
    cudaGetSymbolAddress((void**)&bw2, g_bw2);
    cudaGetSymbolAddress((void**)&deg, g_deg);

    cudaFuncSetAttribute((const void*)gemm_mma_k<128>,
                         cudaFuncAttributeMaxDynamicSharedMemorySize, GEMM_SMEM);
    cudaFuncSetAttribute((const void*)gemm_mma_k<64>,
                         cudaFuncAttributeMaxDynamicSharedMemorySize, GEMM_SMEM);

    // fork-join: CSR chain on a side stream, prep+gemm0 on the main stream
    cudaStream_t side;
    cudaEvent_t ev_fork, ev_join;
    cudaStreamCreateWithFlags(&side, cudaStreamNonBlocking);
    cudaEventCreateWithFlags(&ev_fork, cudaEventDisableTiming);
    cudaEventCreateWithFlags(&ev_join, cudaEventDisableTiming);

    cudaEventRecord(ev_fork, 0);
    cudaStreamWaitEvent(side, ev_fork, 0);

    // side: CSR build
    cudaMemsetAsync(deg, 0, N_NODES * sizeof(int), side);
    hist_k<<<(N_EDGES / 4 + 255) / 256, 256, 0, side>>>(edge_dst);
    scan_k<<<1, 1024, 0, side>>>();
    scatter_k<<<(N_EDGES / 4 + 255) / 256, 256, 0, side>>>(edge_src, edge_dst);
    cudaEventRecord(ev_join, side);

    const int gm = (N_NODES + 127) / 128;        // 79
    const int agg_blocks = (N_NODES + 7) / 8;    // 1250

    // main: prep + layer-0 GEMM run concurrently with CSR build
    prep_all_k<<<(81920 + 255) / 256, 256>>>(W_nei0, W_self0, W_nei1, W_self1, W_nei2, W_self2);
    gemm_mma_k<128><<<dim3(gm, 2), 256, GEMM_SMEM>>>(inputs, bw0, yn, ys);

    cudaStreamWaitEvent(0, ev_join, 0);          // aggregate needs CSR

    aggregate_k<128, true><<<agg_blocks, 256>>>(yn, ys, b0, h0);
    // layer 1
    gemm_mma_k<128><<<dim3(gm, 2), 256, GEMM_SMEM>>>(h0, bw1, yn, ys);
    aggregate_k<128, true><<<agg_blocks, 256>>>(yn, ys, b1, h1);
    // layer 2
    gemm_mma_k<64><<<dim3(gm, 1), 256, GEMM_SMEM>>>(h1, bw2, yn, ys);
    aggregate_k<64, false><<<agg_blocks, 256>>>(yn, ys, b2, out);

    cudaEventDestroy(ev_fork);
    cudaEventDestroy(ev_join);
    cudaStreamDestroy(side);

    (void)in_sizes; (void)n_in; (void)out_size;
}

// round 9
// speedup vs baseline: 1.0608x; 1.0608x over previous
#include <cuda_runtime.h>
#include <cuda_fp16.h>
#include <cstdint>

#define N_NODES 10000
#define N_EDGES 640000
#define K_DIM   128

// ---------------- scratch -------------------------------------------------------
__device__ __align__(128) int    g_deg[N_NODES];
__device__ __align__(128) int    g_off[N_NODES + 1];
__device__ __align__(128) int    g_rank[N_EDGES];       // per-edge rank within dst
__device__ __align__(128) int    g_csr[N_EDGES];
__device__ __align__(128) __half g_yn[N_NODES * 128];   // neighbor projections (fp16)
__device__ __align__(128) float  g_ys[N_NODES * 128];   // self projections (fp32)
__device__ __align__(128) float  g_h0[N_NODES * 128];
__device__ __align__(128) float  g_h1[N_NODES * 128];
__device__ __align__(128) __half g_bw0[256 * 256];      // layer weights: [NOUT][hi128|lo128]
__device__ __align__(128) __half g_bw1[256 * 256];
__device__ __align__(128) __half g_bw2[128 * 256];

// ---------------- small PTX helpers ----------------------------------------------
__device__ __forceinline__ uint32_t smem_u32(const void* p) {
    uint32_t a;
    asm("{ .reg .u64 t; cvta.to.shared.u64 t, %1; cvt.u32.u64 %0, t; }" : "=r"(a) : "l"(p));
    return a;
}
__device__ __forceinline__ void ldsm_x4(uint32_t& r0, uint32_t& r1, uint32_t& r2,
                                        uint32_t& r3, uint32_t addr) {
    asm volatile("ldmatrix.sync.aligned.m8n8.x4.shared.b16 {%0,%1,%2,%3}, [%4];"
                 : "=r"(r0), "=r"(r1), "=r"(r2), "=r"(r3) : "r"(addr));
}
__device__ __forceinline__ void mma16816(float* d, uint32_t a0, uint32_t a1,
                                         uint32_t a2, uint32_t a3,
                                         uint32_t b0, uint32_t b1) {
    asm volatile(
        "mma.sync.aligned.m16n8k16.row.col.f32.f16.f16.f32 "
        "{%0,%1,%2,%3},{%4,%5,%6,%7},{%8,%9},{%0,%1,%2,%3};"
        : "+f"(d[0]), "+f"(d[1]), "+f"(d[2]), "+f"(d[3])
        : "r"(a0), "r"(a1), "r"(a2), "r"(a3), "r"(b0), "r"(b1));
}
__device__ __forceinline__ uint4 ldg_cg_u4(const void* p) {
    uint4 v;
    asm volatile("ld.global.cg.v4.u32 {%0,%1,%2,%3}, [%4];"
                 : "=r"(v.x), "=r"(v.y), "=r"(v.z), "=r"(v.w) : "l"(p));
    return v;
}

// ---------------- prep: build hi/lo weights for all layers ------------------------
__global__ void prep_all_k(const float* __restrict__ Wn0, const float* __restrict__ Ws0,
                           const float* __restrict__ Wn1, const float* __restrict__ Ws1,
                           const float* __restrict__ Wn2, const float* __restrict__ Ws2) {
    int idx = blockIdx.x * blockDim.x + threadIdx.x;
    if (idx >= 81920) return;
    int base, DOUT;
    const float *Wn, *Ws; __half* Bw;
    if (idx < 32768)      { base = idx;         DOUT = 128; Wn = Wn0; Ws = Ws0; Bw = g_bw0; }
    else if (idx < 65536) { base = idx - 32768; DOUT = 128; Wn = Wn1; Ws = Ws1; Bw = g_bw1; }
    else                  { base = idx - 65536; DOUT = 64;  Wn = Wn2; Ws = Ws2; Bw = g_bw2; }
    int n = base >> 7, k = base & 127;
    const float* W = (n < DOUT) ? Wn : Ws;
    int nn = (n < DOUT) ? n : n - DOUT;
    float v = W[(size_t)k * DOUT + nn];
    __half h = __float2half_rn(v);
    __half l = __float2half_rn(v - __half2float(h));
    Bw[(size_t)n * 256 + k]       = h;
    Bw[(size_t)n * 256 + 128 + k] = l;
}

// ---------------- CSR build ----------------------------------------------------
__global__ void hist_k(const int* __restrict__ dst) {
    int e4 = blockIdx.x * blockDim.x + threadIdx.x;
    if (e4 * 4 < N_EDGES) {
        int4 d = ((const int4*)dst)[e4];
        int4 r;
        r.x = atomicAdd(&g_deg[d.x], 1);
        r.y = atomicAdd(&g_deg[d.y], 1);
        r.z = atomicAdd(&g_deg[d.z], 1);
        r.w = atomicAdd(&g_deg[d.w], 1);
        ((int4*)g_rank)[e4] = r;
    }
}

__global__ void scan_k() {
    __shared__ int wsum[32];
    int t = threadIdx.x;
    int base = t * 10;
    int loc[10];
    int s = 0;
    #pragma unroll
    for (int i = 0; i < 10; i++) {
        int idx = base + i;
        int v = (idx < N_NODES) ? g_deg[idx] : 0;
        loc[i] = s; s += v;
    }
    int lane = t & 31, w = t >> 5;
    int x = s;
    #pragma unroll
    for (int o = 1; o < 32; o <<= 1) {
        int y = __shfl_up_sync(0xffffffff, x, o);
        if (lane >= o) x += y;
    }
    if (lane == 31) wsum[w] = x;
    __syncthreads();
    if (w == 0) {
        int y = wsum[lane];
        #pragma unroll
        for (int o = 1; o < 32; o <<= 1) {
            int z = __shfl_up_sync(0xffffffff, y, o);
            if (lane >= o) y += z;
        }
        wsum[lane] = y;
    }
    __syncthreads();
    int warp_excl = (w == 0) ? 0 : wsum[w - 1];
    int texcl = warp_excl + x - s;
    #pragma unroll
    for (int i = 0; i < 10; i++) {
        int idx = base + i;
        if (idx < N_NODES) g_off[idx] = texcl + loc[i];
    }
    if (t == 1023) g_off[N_NODES] = warp_excl + x;
}

__global__ void scatter_k(const int* __restrict__ src, const int* __restrict__ dst) {
    int e4 = blockIdx.x * blockDim.x + threadIdx.x;
    if (e4 * 4 < N_EDGES) {
        int4 s = ((const int4*)src)[e4];
        int4 d = ((const int4*)dst)[e4];
        int4 r = ((const int4*)g_rank)[e4];
        g_csr[__ldg(&g_off[d.x]) + r.x] = s.x;
        g_csr[__ldg(&g_off[d.y]) + r.y] = s.y;
        g_csr[__ldg(&g_off[d.z]) + r.z] = s.z;
        g_csr[__ldg(&g_off[d.w]) + r.w] = s.w;
    }
}

// ---------------- HMMA GEMM: Y = X @ [W_neigh | W_self], hi/lo fp16 split --------
static constexpr int APAD  = 136;
static constexpr int A_HI  = 0;
static constexpr int A_LO  = 128 * APAD * 2;
static constexpr int B_HI  = 2 * 128 * APAD * 2;
static constexpr int B_LO  = B_HI + 128 * APAD * 2;
static constexpr int GEMM_SMEM = B_LO + 128 * APAD * 2;

template <int DOUT>
__global__ void __launch_bounds__(256, 1)
gemm_mma_k(const float* __restrict__ X, const __half* __restrict__ Bw,
           __half* __restrict__ Yn, float* __restrict__ Ys) {
    extern __shared__ char sm[];
    const uint32_t sb = smem_u32(sm);
    const int tid  = threadIdx.x;
    const int lane = tid & 31;
    const int wid  = tid >> 5;
    const int row0 = blockIdx.x * 128;
    const int col0 = blockIdx.y * 128;

    #pragma unroll
    for (int i = 0; i < 16; i++) {
        int idx = i * 256 + tid;
        int r = idx >> 5, q = idx & 31;
        int grow = row0 + r;
        float4 v = make_float4(0.f, 0.f, 0.f, 0.f);
        if (grow < N_NODES) v = *(const float4*)(X + (size_t)grow * K_DIM + q * 4);
        __half hx = __float2half_rn(v.x), hy = __float2half_rn(v.y);
        __half hz = __float2half_rn(v.z), hw = __float2half_rn(v.w);
        __half2 hp0 = __halves2half2(hx, hy), hp1 = __halves2half2(hz, hw);
        __half2 lp0 = __floats2half2_rn(v.x - __half2float(hx), v.y - __half2float(hy));
        __half2 lp1 = __floats2half2_rn(v.z - __half2float(hz), v.w - __half2float(hw));
        uint32_t off = (uint32_t)(r * APAD + q * 4) * 2;
        uint2 uh; uh.x = *(uint32_t*)&hp0; uh.y = *(uint32_t*)&hp1;
        uint2 ul; ul.x = *(uint32_t*)&lp0; ul.y = *(uint32_t*)&lp1;
        *(uint2*)(sm + A_HI + off) = uh;
        *(uint2*)(sm + A_LO + off) = ul;
    }

    #pragma unroll
    for (int i = 0; i < 16; i++) {
        int idx = i * 256 + tid;
        int n = idx >> 5, q = idx & 31;
        uint4 v = *(const uint4*)(Bw + (size_t)(col0 + n) * 256 + q * 8);
        int base = (q < 16) ? B_HI : B_LO;
        uint32_t off = (uint32_t)(n * APAD + (q & 15) * 8) * 2;
        *(uint4*)(sm + base + off) = v;
    }
    __syncthreads();

    const int warp_m = wid >> 1;
    const int warp_n = wid & 1;
    const uint32_t lrow = (uint32_t)(lane & 15);
    const uint32_t lcol = (uint32_t)(lane >> 4) * 16;

    float acc[2][8][4];
    #pragma unroll
    for (int a = 0; a < 2; a++)
        #pragma unroll
        for (int b = 0; b < 8; b++)
            #pragma unroll
            for (int c = 0; c < 4; c++) acc[a][b][c] = 0.f;

    #pragma unroll
    for (int p = 0; p < 3; p++) {
        const uint32_t Ab = sb + (p == 1 ? A_LO : A_HI);
        const uint32_t Bb = sb + (p == 2 ? B_LO : B_HI);
        const uint32_t a0addr = Ab + (warp_m * 32 + lrow) * (APAD * 2) + lcol;
        const uint32_t b0addr = Bb + (warp_n * 64 + lrow) * (APAD * 2) + lcol;
        #pragma unroll
        for (int ks = 0; ks < 8; ks++) {
            const uint32_t koff = (uint32_t)ks * 32;
            uint32_t a0, a1, a2, a3, c0, c1, c2, c3;
            ldsm_x4(a0, a1, a2, a3, a0addr + koff);
            ldsm_x4(c0, c1, c2, c3, a0addr + 16 * (APAD * 2) + koff);
            #pragma unroll
            for (int nb = 0; nb < 4; nb++) {
                uint32_t b0, b1, b2, b3;
                ldsm_x4(b0, b1, b2, b3, b0addr + nb * 16 * (APAD * 2) + koff);
                mma16816(acc[0][nb * 2],     a0, a1, a2, a3, b0, b2);
                mma16816(acc[0][nb * 2 + 1], a0, a1, a2, a3, b1, b3);
                mma16816(acc[1][nb * 2],     c0, c1, c2, c3, b0, b2);
                mma16816(acc[1][nb * 2 + 1], c0, c1, c2, c3, b1, b3);
            }
        }
    }

    #pragma unroll
    for (int mi = 0; mi < 2; mi++) {
        int row_lo = row0 + warp_m * 32 + mi * 16 + (lane >> 2);
        int row_hi = row_lo + 8;
        #pragma unroll
        for (int ni = 0; ni < 8; ni++) {
            float* d = acc[mi][ni];
            int colg = col0 + warp_n * 64 + ni * 8 + (lane & 3) * 2;
            if (colg < DOUT) {
                if (row_lo < N_NODES)
                    *(__half2*)&Yn[(size_t)row_lo * DOUT + colg] = __floats2half2_rn(d[0], d[1]);
                if (row_hi < N_NODES)
                    *(__half2*)&Yn[(size_t)row_hi * DOUT + colg] = __floats2half2_rn(d[2], d[3]);
            } else {
                int c = colg - DOUT;
                if (row_lo < N_NODES)
                    *(float2*)&Ys[(size_t)row_lo * DOUT + c] = make_float2(d[0], d[1]);
                if (row_hi < N_NODES)
                    *(float2*)&Ys[(size_t)row_hi * DOUT + c] = make_float2(d[2], d[3]);
            }
        }
    }
}

// ---------------- aggregate: out = relu?(mean(Yn[csr]) + Ys + bias) -------------
// One warp per node. GP neighbor rows gathered per warp-instruction:
//   DOUT=128: 2 groups x 16 lanes x 16B  (one LDG.128 covers 2 rows/warp)
//   DOUT=64 : 4 groups x  8 lanes x 16B  (4 rows/warp)
// Index selection is a direct per-lane __ldg (uniform within group) — no shfl
// in the address chain. Cross-group combine via shfl_xor AFTER the loop.
template <int DOUT, bool RELU>
__global__ void aggregate_k(const __half* __restrict__ Yn,
                            const float*  __restrict__ Ys,
                            const float*  __restrict__ bias,
                            float*        __restrict__ out) {
    constexpr int GP = (DOUT == 128) ? 2 : 4;     // rows per warp-instruction
    constexpr int LPR = 32 / GP;                  // lanes per row
    int gw = (blockIdx.x * blockDim.x + threadIdx.x) >> 5;
    if (gw >= N_NODES) return;
    int lane = threadIdx.x & 31;
    const int g  = lane / LPR;                    // group = neighbor slot
    const int fl = lane % LPR;                    // feature lane (8 halves each)

    int beg = g_off[gw], end = g_off[gw + 1];
    float acc[8];
    #pragma unroll
    for (int v = 0; v < 8; v++) acc[v] = 0.f;

    const __half* base = Yn + fl * 8;             // this lane's 16B slice
    int j = beg;

    // 4 packets in flight (4*GP neighbors per iteration)
    for (; j + GP * 4 <= end; j += GP * 4) {
        int s[4];
        #pragma unroll
        for (int u = 0; u < 4; u++) s[u] = __ldg(&g_csr[j + u * GP + g]);
        uint4 q[4];
        #pragma unroll
        for (int u = 0; u < 4; u++) q[u] = ldg_cg_u4(base + (size_t)s[u] * DOUT);
        #pragma unroll
        for (int u = 0; u < 4; u++) {
            __half2* h = (__half2*)&q[u];
            #pragma unroll
            for (int t = 0; t < 4; t++) {
                float2 f = __half22float2(h[t]);
                acc[2 * t] += f.x; acc[2 * t + 1] += f.y;
            }
        }
    }
    // single packets
    for (; j + GP <= end; j += GP) {
        int s = __ldg(&g_csr[j + g]);
        uint4 q = ldg_cg_u4(base + (size_t)s * DOUT);
        __half2* h = (__half2*)&q;
        #pragma unroll
        for (int t = 0; t < 4; t++) {
            float2 f = __half22float2(h[t]);
            acc[2 * t] += f.x; acc[2 * t + 1] += f.y;
        }
    }
    // partial packet: only groups < rem contribute
    int rem = end - j;
    if (g < rem) {
        int s = __ldg(&g_csr[j + g]);
        uint4 q = ldg_cg_u4(base + (size_t)s * DOUT);
        __half2* h = (__half2*)&q;
        #pragma unroll
        for (int t = 0; t < 4; t++) {
            float2 f = __half22float2(h[t]);
            acc[2 * t] += f.x; acc[2 * t + 1] += f.y;
        }
    }

    // combine groups (outside the load chain)
    if constexpr (GP == 4) {
        #pragma unroll
        for (int v = 0; v < 8; v++) acc[v] += __shfl_xor_sync(0xffffffff, acc[v], 8);
    }
    #pragma unroll
    for (int v = 0; v < 8; v++) acc[v] += __shfl_xor_sync(0xffffffff, acc[v], 16);

    // group 0 lanes write 8 consecutive dims each
    if (g == 0) {
        float inv = 1.0f / fmaxf((float)(end - beg), 1.0f);
        #pragma unroll
        for (int t = 0; t < 2; t++) {
            int d0 = fl * 8 + t * 4;
            float4 s  = *(const float4*)(Ys + (size_t)gw * DOUT + d0);
            float4 bb = *(const float4*)(bias + d0);
            float4 o;
            o.x = acc[4 * t + 0] * inv + s.x + bb.x;
            o.y = acc[4 * t + 1] * inv + s.y + bb.y;
            o.z = acc[4 * t + 2] * inv + s.z + bb.z;
            o.w = acc[4 * t + 3] * inv + s.w + bb.w;
            if (RELU) {
                o.x = fmaxf(o.x, 0.f); o.y = fmaxf(o.y, 0.f);
                o.z = fmaxf(o.z, 0.f); o.w = fmaxf(o.w, 0.f);
            }
            *(float4*)(out + (size_t)gw * DOUT + d0) = o;
        }
    }
}

// ---------------- launcher -------------------------------------------------------
extern "C" void kernel_launch(void* const* d_in, const int* in_sizes, int n_in,
                              void* d_out, int out_size) {
    const float* inputs  = (const float*)d_in[0];
    const float* W_self0 = (const float*)d_in[1];
    const float* W_nei0  = (const float*)d_in[2];
    const float* b0      = (const float*)d_in[3];
    const float* W_self1 = (const float*)d_in[4];
    const float* W_nei1  = (const float*)d_in[5];
    const float* b1      = (const float*)d_in[6];
    const float* W_self2 = (const float*)d_in[7];
    const float* W_nei2  = (const float*)d_in[8];
    const float* b2      = (const float*)d_in[9];
    const int* edge_src  = (const int*)d_in[10];
    const int* edge_dst  = (const int*)d_in[11];
    float* out = (float*)d_out;

    __half *yn, *bw0, *bw1, *bw2; float *ys, *h0, *h1; int* deg;
    cudaGetSymbolAddress((void**)&yn,  g_yn);
    cudaGetSymbolAddress((void**)&ys,  g_ys);
    cudaGetSymbolAddress((void**)&h0,  g_h0);
    cudaGetSymbolAddress((void**)&h1,  g_h1);
    cudaGetSymbolAddress((void**)&bw0, g_bw0);
    cudaGetSymbolAddress((void**)&bw1, g_bw1);
    cudaGetSymbolAddress((void**)&bw2, g_bw2);
    cudaGetSymbolAddress((void**)&deg, g_deg);

    cudaFuncSetAttribute((const void*)gemm_mma_k<128>,
                         cudaFuncAttributeMaxDynamicSharedMemorySize, GEMM_SMEM);
    cudaFuncSetAttribute((const void*)gemm_mma_k<64>,
                         cudaFuncAttributeMaxDynamicSharedMemorySize, GEMM_SMEM);

    // fork-join: CSR chain on a side stream, prep+gemm0 on the main stream
    cudaStream_t side;
    cudaEvent_t ev_fork, ev_join;
    cudaStreamCreateWithFlags(&side, cudaStreamNonBlocking);
    cudaEventCreateWithFlags(&ev_fork, cudaEventDisableTiming);
    cudaEventCreateWithFlags(&ev_join, cudaEventDisableTiming);

    cudaEventRecord(ev_fork, 0);
    cudaStreamWaitEvent(side, ev_fork, 0);

    // side: CSR build
    cudaMemsetAsync(deg, 0, N_NODES * sizeof(int), side);
    hist_k<<<(N_EDGES / 4 + 255) / 256, 256, 0, side>>>(edge_dst);
    scan_k<<<1, 1024, 0, side>>>();
    scatter_k<<<(N_EDGES / 4 + 255) / 256, 256, 0, side>>>(edge_src, edge_dst);
    cudaEventRecord(ev_join, side);

    const int gm = (N_NODES + 127) / 128;        // 79
    const int agg_blocks = (N_NODES + 7) / 8;    // 1250

    // main: prep + layer-0 GEMM run concurrently with CSR build
    prep_all_k<<<(81920 + 255) / 256, 256>>>(W_nei0, W_self0, W_nei1, W_self1, W_nei2, W_self2);
    gemm_mma_k<128><<<dim3(gm, 2), 256, GEMM_SMEM>>>(inputs, bw0, yn, ys);

    cudaStreamWaitEvent(0, ev_join, 0);          // aggregate needs CSR

    aggregate_k<128, true><<<agg_blocks, 256>>>(yn, ys, b0, h0);
    // layer 1
    gemm_mma_k<128><<<dim3(gm, 2), 256, GEMM_SMEM>>>(h0, bw1, yn, ys);
    aggregate_k<128, true><<<agg_blocks, 256>>>(yn, ys, b1, h1);
    // layer 2
    gemm_mma_k<64><<<dim3(gm, 1), 256, GEMM_SMEM>>>(h1, bw2, yn, ys);
    aggregate_k<64, false><<<agg_blocks, 256>>>(yn, ys, b2, out);

    cudaEventDestroy(ev_fork);
    cudaEventDestroy(ev_join);
    cudaStreamDestroy(side);

    (void)in_sizes; (void)n_in; (void)out_size;
}

// round 10
// speedup vs baseline: 1.0953x; 1.0326x over previous
#include <cuda_runtime.h>
#include <cuda_fp16.h>
#include <cstdint>

#define N_NODES 10000
#define N_EDGES 640000
#define K_DIM   128

// ---------------- scratch -------------------------------------------------------
__device__ __align__(128) int    g_deg[N_NODES];
__device__ __align__(128) int    g_off[N_NODES + 1];
__device__ __align__(128) int    g_rank[N_EDGES];       // per-edge rank within dst
__device__ __align__(128) int    g_csr[N_EDGES];
__device__ __align__(128) __half g_yn[N_NODES * 128];   // neighbor projections (fp16)
__device__ __align__(128) float  g_ys[N_NODES * 128];   // self projections (fp32)
__device__ __align__(128) float  g_h0[N_NODES * 128];
__device__ __align__(128) float  g_h1[N_NODES * 128];
__device__ __align__(128) __half g_bw0[256 * 256];      // layer weights: [NOUT][hi128|lo128]
__device__ __align__(128) __half g_bw1[256 * 256];
__device__ __align__(128) __half g_bw2[128 * 256];

// ---------------- small PTX helpers ----------------------------------------------
__device__ __forceinline__ uint32_t smem_u32(const void* p) {
    uint32_t a;
    asm("{ .reg .u64 t; cvta.to.shared.u64 t, %1; cvt.u32.u64 %0, t; }" : "=r"(a) : "l"(p));
    return a;
}
__device__ __forceinline__ void ldsm_x4(uint32_t& r0, uint32_t& r1, uint32_t& r2,
                                        uint32_t& r3, uint32_t addr) {
    asm volatile("ldmatrix.sync.aligned.m8n8.x4.shared.b16 {%0,%1,%2,%3}, [%4];"
                 : "=r"(r0), "=r"(r1), "=r"(r2), "=r"(r3) : "r"(addr));
}
__device__ __forceinline__ void mma16816(float* d, uint32_t a0, uint32_t a1,
                                         uint32_t a2, uint32_t a3,
                                         uint32_t b0, uint32_t b1) {
    asm volatile(
        "mma.sync.aligned.m16n8k16.row.col.f32.f16.f16.f32 "
        "{%0,%1,%2,%3},{%4,%5,%6,%7},{%8,%9},{%0,%1,%2,%3};"
        : "+f"(d[0]), "+f"(d[1]), "+f"(d[2]), "+f"(d[3])
        : "r"(a0), "r"(a1), "r"(a2), "r"(a3), "r"(b0), "r"(b1));
}
__device__ __forceinline__ uint4 ldg_cg_u4(const void* p) {
    uint4 v;
    asm volatile("ld.global.cg.v4.u32 {%0,%1,%2,%3}, [%4];"
                 : "=r"(v.x), "=r"(v.y), "=r"(v.z), "=r"(v.w) : "l"(p));
    return v;
}

// ---------------- prep: build hi/lo weights for all layers ------------------------
__global__ void prep_all_k(const float* __restrict__ Wn0, const float* __restrict__ Ws0,
                           const float* __restrict__ Wn1, const float* __restrict__ Ws1,
                           const float* __restrict__ Wn2, const float* __restrict__ Ws2) {
    int idx = blockIdx.x * blockDim.x + threadIdx.x;
    if (idx >= 81920) return;
    int base, DOUT;
    const float *Wn, *Ws; __half* Bw;
    if (idx < 32768)      { base = idx;         DOUT = 128; Wn = Wn0; Ws = Ws0; Bw = g_bw0; }
    else if (idx < 65536) { base = idx - 32768; DOUT = 128; Wn = Wn1; Ws = Ws1; Bw = g_bw1; }
    else                  { base = idx - 65536; DOUT = 64;  Wn = Wn2; Ws = Ws2; Bw = g_bw2; }
    int n = base >> 7, k = base & 127;
    const float* W = (n < DOUT) ? Wn : Ws;
    int nn = (n < DOUT) ? n : n - DOUT;
    float v = W[(size_t)k * DOUT + nn];
    __half h = __float2half_rn(v);
    __half l = __float2half_rn(v - __half2float(h));
    Bw[(size_t)n * 256 + k]       = h;
    Bw[(size_t)n * 256 + 128 + k] = l;
}

// ---------------- CSR build ----------------------------------------------------
// 8 edges per thread: more outstanding atomics (latency-bound kernel).
__global__ void hist_k(const int* __restrict__ dst) {
    int t = blockIdx.x * blockDim.x + threadIdx.x;
    int e4 = t * 2;
    if (e4 * 4 < N_EDGES) {
        int4 d0 = ((const int4*)dst)[e4];
        int4 d1 = ((const int4*)dst)[e4 + 1];
        int4 r0, r1;
        r0.x = atomicAdd(&g_deg[d0.x], 1);
        r0.y = atomicAdd(&g_deg[d0.y], 1);
        r0.z = atomicAdd(&g_deg[d0.z], 1);
        r0.w = atomicAdd(&g_deg[d0.w], 1);
        r1.x = atomicAdd(&g_deg[d1.x], 1);
        r1.y = atomicAdd(&g_deg[d1.y], 1);
        r1.z = atomicAdd(&g_deg[d1.z], 1);
        r1.w = atomicAdd(&g_deg[d1.w], 1);
        ((int4*)g_rank)[e4]     = r0;
        ((int4*)g_rank)[e4 + 1] = r1;
    }
}

__global__ void scan_k() {
    __shared__ int wsum[32];
    int t = threadIdx.x;
    int base = t * 10;
    int loc[10];
    int s = 0;
    #pragma unroll
    for (int i = 0; i < 10; i++) {
        int idx = base + i;
        int v = (idx < N_NODES) ? g_deg[idx] : 0;
        loc[i] = s; s += v;
    }
    int lane = t & 31, w = t >> 5;
    int x = s;
    #pragma unroll
    for (int o = 1; o < 32; o <<= 1) {
        int y = __shfl_up_sync(0xffffffff, x, o);
        if (lane >= o) x += y;
    }
    if (lane == 31) wsum[w] = x;
    __syncthreads();
    if (w == 0) {
        int y = wsum[lane];
        #pragma unroll
        for (int o = 1; o < 32; o <<= 1) {
            int z = __shfl_up_sync(0xffffffff, y, o);
            if (lane >= o) y += z;
        }
        wsum[lane] = y;
    }
    __syncthreads();
    int warp_excl = (w == 0) ? 0 : wsum[w - 1];
    int texcl = warp_excl + x - s;
    #pragma unroll
    for (int i = 0; i < 10; i++) {
        int idx = base + i;
        if (idx < N_NODES) g_off[idx] = texcl + loc[i];
    }
    if (t == 1023) g_off[N_NODES] = warp_excl + x;
}

// 8 edges per thread, no atomics.
__global__ void scatter_k(const int* __restrict__ src, const int* __restrict__ dst) {
    int t = blockIdx.x * blockDim.x + threadIdx.x;
    int e4 = t * 2;
    if (e4 * 4 < N_EDGES) {
        int4 s0 = ((const int4*)src)[e4];
        int4 s1 = ((const int4*)src)[e4 + 1];
        int4 d0 = ((const int4*)dst)[e4];
        int4 d1 = ((const int4*)dst)[e4 + 1];
        int4 r0 = ((const int4*)g_rank)[e4];
        int4 r1 = ((const int4*)g_rank)[e4 + 1];
        int o0 = __ldg(&g_off[d0.x]);
        int o1 = __ldg(&g_off[d0.y]);
        int o2 = __ldg(&g_off[d0.z]);
        int o3 = __ldg(&g_off[d0.w]);
        int o4 = __ldg(&g_off[d1.x]);
        int o5 = __ldg(&g_off[d1.y]);
        int o6 = __ldg(&g_off[d1.z]);
        int o7 = __ldg(&g_off[d1.w]);
        g_csr[o0 + r0.x] = s0.x;
        g_csr[o1 + r0.y] = s0.y;
        g_csr[o2 + r0.z] = s0.z;
        g_csr[o3 + r0.w] = s0.w;
        g_csr[o4 + r1.x] = s1.x;
        g_csr[o5 + r1.y] = s1.y;
        g_csr[o6 + r1.z] = s1.z;
        g_csr[o7 + r1.w] = s1.w;
    }
}

// ---------------- HMMA GEMM: Y = X @ [W_neigh | W_self], hi/lo fp16 split --------
static constexpr int APAD  = 136;
static constexpr int A_HI  = 0;
static constexpr int A_LO  = 128 * APAD * 2;
static constexpr int B_HI  = 2 * 128 * APAD * 2;
static constexpr int B_LO  = B_HI + 128 * APAD * 2;
static constexpr int GEMM_SMEM = B_LO + 128 * APAD * 2;

template <int DOUT>
__global__ void __launch_bounds__(256, 1)
gemm_mma_k(const float* __restrict__ X, const __half* __restrict__ Bw,
           __half* __restrict__ Yn, float* __restrict__ Ys) {
    extern __shared__ char sm[];
    const uint32_t sb = smem_u32(sm);
    const int tid  = threadIdx.x;
    const int lane = tid & 31;
    const int wid  = tid >> 5;
    const int row0 = blockIdx.x * 128;
    const int col0 = blockIdx.y * 128;

    #pragma unroll
    for (int i = 0; i < 16; i++) {
        int idx = i * 256 + tid;
        int r = idx >> 5, q = idx & 31;
        int grow = row0 + r;
        float4 v = make_float4(0.f, 0.f, 0.f, 0.f);
        if (grow < N_NODES) v = *(const float4*)(X + (size_t)grow * K_DIM + q * 4);
        __half hx = __float2half_rn(v.x), hy = __float2half_rn(v.y);
        __half hz = __float2half_rn(v.z), hw = __float2half_rn(v.w);
        __half2 hp0 = __halves2half2(hx, hy), hp1 = __halves2half2(hz, hw);
        __half2 lp0 = __floats2half2_rn(v.x - __half2float(hx), v.y - __half2float(hy));
        __half2 lp1 = __floats2half2_rn(v.z - __half2float(hz), v.w - __half2float(hw));
        uint32_t off = (uint32_t)(r * APAD + q * 4) * 2;
        uint2 uh; uh.x = *(uint32_t*)&hp0; uh.y = *(uint32_t*)&hp1;
        uint2 ul; ul.x = *(uint32_t*)&lp0; ul.y = *(uint32_t*)&lp1;
        *(uint2*)(sm + A_HI + off) = uh;
        *(uint2*)(sm + A_LO + off) = ul;
    }

    #pragma unroll
    for (int i = 0; i < 16; i++) {
        int idx = i * 256 + tid;
        int n = idx >> 5, q = idx & 31;
        uint4 v = *(const uint4*)(Bw + (size_t)(col0 + n) * 256 + q * 8);
        int base = (q < 16) ? B_HI : B_LO;
        uint32_t off = (uint32_t)(n * APAD + (q & 15) * 8) * 2;
        *(uint4*)(sm + base + off) = v;
    }
    __syncthreads();

    const int warp_m = wid >> 1;
    const int warp_n = wid & 1;
    const uint32_t lrow = (uint32_t)(lane & 15);
    const uint32_t lcol = (uint32_t)(lane >> 4) * 16;

    float acc[2][8][4];
    #pragma unroll
    for (int a = 0; a < 2; a++)
        #pragma unroll
        for (int b = 0; b < 8; b++)
            #pragma unroll
            for (int c = 0; c < 4; c++) acc[a][b][c] = 0.f;

    #pragma unroll
    for (int p = 0; p < 3; p++) {
        const uint32_t Ab = sb + (p == 1 ? A_LO : A_HI);
        const uint32_t Bb = sb + (p == 2 ? B_LO : B_HI);
        const uint32_t a0addr = Ab + (warp_m * 32 + lrow) * (APAD * 2) + lcol;
        const uint32_t b0addr = Bb + (warp_n * 64 + lrow) * (APAD * 2) + lcol;
        #pragma unroll
        for (int ks = 0; ks < 8; ks++) {
            const uint32_t koff = (uint32_t)ks * 32;
            uint32_t a0, a1, a2, a3, c0, c1, c2, c3;
            ldsm_x4(a0, a1, a2, a3, a0addr + koff);
            ldsm_x4(c0, c1, c2, c3, a0addr + 16 * (APAD * 2) + koff);
            #pragma unroll
            for (int nb = 0; nb < 4; nb++) {
                uint32_t b0, b1, b2, b3;
                ldsm_x4(b0, b1, b2, b3, b0addr + nb * 16 * (APAD * 2) + koff);
                mma16816(acc[0][nb * 2],     a0, a1, a2, a3, b0, b2);
                mma16816(acc[0][nb * 2 + 1], a0, a1, a2, a3, b1, b3);
                mma16816(acc[1][nb * 2],     c0, c1, c2, c3, b0, b2);
                mma16816(acc[1][nb * 2 + 1], c0, c1, c2, c3, b1, b3);
            }
        }
    }

    #pragma unroll
    for (int mi = 0; mi < 2; mi++) {
        int row_lo = row0 + warp_m * 32 + mi * 16 + (lane >> 2);
        int row_hi = row_lo + 8;
        #pragma unroll
        for (int ni = 0; ni < 8; ni++) {
            float* d = acc[mi][ni];
            int colg = col0 + warp_n * 64 + ni * 8 + (lane & 3) * 2;
            if (colg < DOUT) {
                if (row_lo < N_NODES)
                    *(__half2*)&Yn[(size_t)row_lo * DOUT + colg] = __floats2half2_rn(d[0], d[1]);
                if (row_hi < N_NODES)
                    *(__half2*)&Yn[(size_t)row_hi * DOUT + colg] = __floats2half2_rn(d[2], d[3]);
            } else {
                int c = colg - DOUT;
                if (row_lo < N_NODES)
                    *(float2*)&Ys[(size_t)row_lo * DOUT + c] = make_float2(d[0], d[1]);
                if (row_hi < N_NODES)
                    *(float2*)&Ys[(size_t)row_hi * DOUT + c] = make_float2(d[2], d[3]);
            }
        }
    }
}

// ---------------- aggregate: out = relu?(mean(Yn[csr]) + Ys + bias) -------------
// One warp per node. GP rows per warp-instruction; 8 packets (8*GP rows) in
// flight per iteration for deep MLP. No shfl in the address chain.
template <int DOUT, bool RELU>
__global__ void aggregate_k(const __half* __restrict__ Yn,
                            const float*  __restrict__ Ys,
                            const float*  __restrict__ bias,
                            float*        __restrict__ out) {
    constexpr int GP = (DOUT == 128) ? 2 : 4;     // rows per warp-instruction
    constexpr int LPR = 32 / GP;                  // lanes per row
    int gw = (blockIdx.x * blockDim.x + threadIdx.x) >> 5;
    if (gw >= N_NODES) return;
    int lane = threadIdx.x & 31;
    const int g  = lane / LPR;
    const int fl = lane % LPR;

    int beg = g_off[gw], end = g_off[gw + 1];
    float acc[8];
    #pragma unroll
    for (int v = 0; v < 8; v++) acc[v] = 0.f;

    const __half* base = Yn + fl * 8;
    int j = beg;

    // 8 packets in flight (8*GP neighbors per iteration)
    for (; j + GP * 8 <= end; j += GP * 8) {
        int s[8];
        #pragma unroll
        for (int u = 0; u < 8; u++) s[u] = __ldg(&g_csr[j + u * GP + g]);
        uint4 q[8];
        #pragma unroll
        for (int u = 0; u < 8; u++) q[u] = ldg_cg_u4(base + (size_t)s[u] * DOUT);
        #pragma unroll
        for (int u = 0; u < 8; u++) {
            __half2* h = (__half2*)&q[u];
            #pragma unroll
            for (int t = 0; t < 4; t++) {
                float2 f = __half22float2(h[t]);
                acc[2 * t] += f.x; acc[2 * t + 1] += f.y;
            }
        }
    }
    // single packets
    for (; j + GP <= end; j += GP) {
        int s = __ldg(&g_csr[j + g]);
        uint4 q = ldg_cg_u4(base + (size_t)s * DOUT);
        __half2* h = (__half2*)&q;
        #pragma unroll
        for (int t = 0; t < 4; t++) {
            float2 f = __half22float2(h[t]);
            acc[2 * t] += f.x; acc[2 * t + 1] += f.y;
        }
    }
    // partial packet
    int rem = end - j;
    if (g < rem) {
        int s = __ldg(&g_csr[j + g]);
        uint4 q = ldg_cg_u4(base + (size_t)s * DOUT);
        __half2* h = (__half2*)&q;
        #pragma unroll
        for (int t = 0; t < 4; t++) {
            float2 f = __half22float2(h[t]);
            acc[2 * t] += f.x; acc[2 * t + 1] += f.y;
        }
    }

    // combine groups (outside the load chain)
    if constexpr (GP == 4) {
        #pragma unroll
        for (int v = 0; v < 8; v++) acc[v] += __shfl_xor_sync(0xffffffff, acc[v], 8);
    }
    #pragma unroll
    for (int v = 0; v < 8; v++) acc[v] += __shfl_xor_sync(0xffffffff, acc[v], 16);

    if (g == 0) {
        float inv = 1.0f / fmaxf((float)(end - beg), 1.0f);
        #pragma unroll
        for (int t = 0; t < 2; t++) {
            int d0 = fl * 8 + t * 4;
            float4 s  = *(const float4*)(Ys + (size_t)gw * DOUT + d0);
            float4 bb = *(const float4*)(bias + d0);
            float4 o;
            o.x = acc[4 * t + 0] * inv + s.x + bb.x;
            o.y = acc[4 * t + 1] * inv + s.y + bb.y;
            o.z = acc[4 * t + 2] * inv + s.z + bb.z;
            o.w = acc[4 * t + 3] * inv + s.w + bb.w;
            if (RELU) {
                o.x = fmaxf(o.x, 0.f); o.y = fmaxf(o.y, 0.f);
                o.z = fmaxf(o.z, 0.f); o.w = fmaxf(o.w, 0.f);
            }
            *(float4*)(out + (size_t)gw * DOUT + d0) = o;
        }
    }
}

// ---------------- launcher -------------------------------------------------------
extern "C" void kernel_launch(void* const* d_in, const int* in_sizes, int n_in,
                              void* d_out, int out_size) {
    const float* inputs  = (const float*)d_in[0];
    const float* W_self0 = (const float*)d_in[1];
    const float* W_nei0  = (const float*)d_in[2];
    const float* b0      = (const float*)d_in[3];
    const float* W_self1 = (const float*)d_in[4];
    const float* W_nei1  = (const float*)d_in[5];
    const float* b1      = (const float*)d_in[6];
    const float* W_self2 = (const float*)d_in[7];
    const float* W_nei2  = (const float*)d_in[8];
    const float* b2      = (const float*)d_in[9];
    const int* edge_src  = (const int*)d_in[10];
    const int* edge_dst  = (const int*)d_in[11];
    float* out = (float*)d_out;

    __half *yn, *bw0, *bw1, *bw2; float *ys, *h0, *h1; int* deg;
    cudaGetSymbolAddress((void**)&yn,  g_yn);
    cudaGetSymbolAddress((void**)&ys,  g_ys);
    cudaGetSymbolAddress((void**)&h0,  g_h0);
    cudaGetSymbolAddress((void**)&h1,  g_h1);
    cudaGetSymbolAddress((void**)&bw0, g_bw0);
    cudaGetSymbolAddress((void**)&bw1, g_bw1);
    cudaGetSymbolAddress((void**)&bw2, g_bw2);
    cudaGetSymbolAddress((void**)&deg, g_deg);

    cudaFuncSetAttribute((const void*)gemm_mma_k<128>,
                         cudaFuncAttributeMaxDynamicSharedMemorySize, GEMM_SMEM);
    cudaFuncSetAttribute((const void*)gemm_mma_k<64>,
                         cudaFuncAttributeMaxDynamicSharedMemorySize, GEMM_SMEM);

    // fork-join: CSR chain on a side stream, prep+gemm0 on the main stream
    cudaStream_t side;
    cudaEvent_t ev_fork, ev_join;
    cudaStreamCreateWithFlags(&side, cudaStreamNonBlocking);
    cudaEventCreateWithFlags(&ev_fork, cudaEventDisableTiming);
    cudaEventCreateWithFlags(&ev_join, cudaEventDisableTiming);

    cudaEventRecord(ev_fork, 0);
    cudaStreamWaitEvent(side, ev_fork, 0);

    // side: CSR build (8 edges/thread)
    cudaMemsetAsync(deg, 0, N_NODES * sizeof(int), side);
    hist_k<<<(N_EDGES / 8 + 255) / 256, 256, 0, side>>>(edge_dst);
    scan_k<<<1, 1024, 0, side>>>();
    scatter_k<<<(N_EDGES / 8 + 255) / 256, 256, 0, side>>>(edge_src, edge_dst);
    cudaEventRecord(ev_join, side);

    const int gm = (N_NODES + 127) / 128;        // 79
    const int agg_blocks = (N_NODES + 7) / 8;    // 1250

    // main: prep + layer-0 GEMM run concurrently with CSR build
    prep_all_k<<<(81920 + 255) / 256, 256>>>(W_nei0, W_self0, W_nei1, W_self1, W_nei2, W_self2);
    gemm_mma_k<128><<<dim3(gm, 2), 256, GEMM_SMEM>>>(inputs, bw0, yn, ys);

    cudaStreamWaitEvent(0, ev_join, 0);          // aggregate needs CSR

    aggregate_k<128, true><<<agg_blocks, 256>>>(yn, ys, b0, h0);
    // layer 1
    gemm_mma_k<128><<<dim3(gm, 2), 256, GEMM_SMEM>>>(h0, bw1, yn, ys);
    aggregate_k<128, true><<<agg_blocks, 256>>>(yn, ys, b1, h1);
    // layer 2
    gemm_mma_k<64><<<dim3(gm, 1), 256, GEMM_SMEM>>>(h1, bw2, yn, ys);
    aggregate_k<64, false><<<agg_blocks, 256>>>(yn, ys, b2, out);

    cudaEventDestroy(ev_fork);
    cudaEventDestroy(ev_join);
    cudaStreamDestroy(side);

    (void)in_sizes; (void)n_in; (void)out_size;
}